// round 15
// baseline (speedup 1.0000x reference)
#include <cuda_runtime.h>
#include <cuda_bf16.h>

// ActionEncoder: out[b] = tanh(b_t + sum_s W_t[:, s*64 + idx[b,s]])
// Pairs layout (2 adjacent samples/thread, int4+int2 coalesced loads) +
// STG.256 for both results (R13, best measured).
// R14: Tb compressed to 65 entries with Tb[0]=0; t=0 lanes all read Tb[0]
// (smem broadcast, free) instead of random zero slots -> fewer LDS conflict
// phases. tanh = 1 - 2/(e^{2x}+1) with e^{2x} = ex2(a+c) (tables store
// 2*log2e*(W+b)); 2 MUFU per component, shortest chain.

#define MAX_N 64

__device__ __forceinline__ float ex2f(float x) {
    float r;
    asm("ex2.approx.f32 %0, %1;" : "=f"(r) : "f"(x));
    return r;
}
__device__ __forceinline__ float rcpf(float x) {
    float r;
    asm("rcp.approx.f32 %0, %1;" : "=f"(r) : "f"(x));
    return r;
}
__device__ __forceinline__ float tanh_from_s(float s) {
    // s = 2*log2e*x ; tanh(x) = 1 - 2/(ex2(s)+1)
    float e = ex2f(s);
    return fmaf(-2.f, rcpf(e + 1.f), 1.f);
}

__device__ __forceinline__ float4 enc(const float4* Ta, const float4* Tb,
                                      int t, int i0, int i1) {
    float4 a = Ta[(t << 6) + i0];          // scaled slot0 + bias
    float4 c = Tb[t ? (1 + i1) : 0];       // scaled slot1; broadcast zero for t=0
    return make_float4(tanh_from_s(a.x + c.x), tanh_from_s(a.y + c.y),
                       tanh_from_s(a.z + c.z), tanh_from_s(a.w + c.w));
}

__global__ __launch_bounds__(256)
void action_encoder_kernel(const int4* __restrict__ idx2,    // [B/2] two (i0,i1) pairs
                           const int2* __restrict__ types2,  // [B/2] two types
                           const float* __restrict__ W0,     // [4,64]
                           const float* __restrict__ b0,     // [4]
                           const float* __restrict__ W1,     // [4,128]
                           const float* __restrict__ b1,     // [4]
                           float4* __restrict__ out,         // [B]
                           int Bpairs) {
    __shared__ float4 Ta[2 * MAX_N];   // [t*64+i0]: 2*log2e*(W slot0 + b)
    __shared__ float4 Tb[1 + MAX_N];   // [0]=0 ; [1+i1]: 2*log2e*(W1 slot1)
    const float S = 2.8853900817779268f;   // 2*log2(e)
    int tid = threadIdx.x;
    if (tid < MAX_N) {
        Ta[tid] = make_float4(S * (W0[0*64 + tid] + b0[0]),
                              S * (W0[1*64 + tid] + b0[1]),
                              S * (W0[2*64 + tid] + b0[2]),
                              S * (W0[3*64 + tid] + b0[3]));
        Tb[1 + tid] = make_float4(S * W1[0*128 + 64 + tid],
                                  S * W1[1*128 + 64 + tid],
                                  S * W1[2*128 + 64 + tid],
                                  S * W1[3*128 + 64 + tid]);
    } else if (tid < 2 * MAX_N) {
        int j = tid - MAX_N;
        Ta[tid] = make_float4(S * (W1[0*128 + j] + b1[0]),
                              S * (W1[1*128 + j] + b1[1]),
                              S * (W1[2*128 + j] + b1[2]),
                              S * (W1[3*128 + j] + b1[3]));
        if (j == 0) Tb[0] = make_float4(0.f, 0.f, 0.f, 0.f);
    }
    __syncthreads();

    int p = blockIdx.x * blockDim.x + tid;   // pair index
    if (p >= Bpairs) return;

    int4 ix = idx2[p];    // one coalesced 16B load: both samples' indices
    int2 tt = types2[p];  // one coalesced  8B load: both types

    float4 r0 = enc(Ta, Tb, tt.x, ix.x, ix.y);
    float4 r1 = enc(Ta, Tb, tt.y, ix.z, ix.w);

    // One 256-bit store for both adjacent float4 results (32B-aligned).
    float* o = (float*)(out + 2 * p);
    asm volatile("st.global.v8.f32 [%0], {%1,%2,%3,%4,%5,%6,%7,%8};"
                 :: "l"(o),
                    "f"(r0.x), "f"(r0.y), "f"(r0.z), "f"(r0.w),
                    "f"(r1.x), "f"(r1.y), "f"(r1.z), "f"(r1.w)
                 : "memory");
}

extern "C" void kernel_launch(void* const* d_in, const int* in_sizes, int n_in,
                              void* d_out, int out_size) {
    // metadata order: action_indecies, action_n_obj, action_types, W0, b0, W1, b1
    const int4*  idx2   = (const int4*) d_in[0];
    const int2*  types2 = (const int2*) d_in[2];
    const float* W0     = (const float*)d_in[3];
    const float* b0     = (const float*)d_in[4];
    const float* W1     = (const float*)d_in[5];
    const float* b1     = (const float*)d_in[6];
    float4* out = (float4*)d_out;

    int B = in_sizes[2];      // 524288 (even)
    int Bpairs = B >> 1;      // 262144

    int threads = 256;
    int blocks  = (Bpairs + threads - 1) / threads;  // 1024
    action_encoder_kernel<<<blocks, threads>>>(idx2, types2, W0, b0, W1, b1,
                                               out, Bpairs);
}